// round 1
// baseline (speedup 1.0000x reference)
#include <cuda_runtime.h>
#include <cuda_bf16.h>

// NoQmix_74560632258885
//
// Reference math collapses: attention = softmax(e, axis=1) is column-stochastic
// (sum over i == 1 for every column j, including fully-masked columns, which
// softmax to uniform). Therefore
//   q_tot[b] = sum_{i,j} att[b,i,j] * qs[b,j] = sum_j qs[b,j].
// The GEMM / GAT / softmax pipeline is algebraically dead; the exact output is
// the per-batch sum of agent_qs [B=4096, N=64] -> [B].
//
// Kernel: one warp per batch. Lane l loads qs[b*64+l] and qs[b*64+32+l]
// (coalesced), butterfly warp reduction, lane 0 writes out[b].

static constexpr int N_AGENTS = 64;

__global__ void noqmix_rowsum_kernel(const float* __restrict__ qs,
                                     float* __restrict__ out,
                                     int nbatch) {
    const int warp_id = (blockIdx.x * blockDim.x + threadIdx.x) >> 5;
    const int lane    = threadIdx.x & 31;
    if (warp_id >= nbatch) return;

    const float* row = qs + (long long)warp_id * N_AGENTS;
    float v = row[lane] + row[lane + 32];

    // butterfly reduction across the warp
    #pragma unroll
    for (int off = 16; off > 0; off >>= 1)
        v += __shfl_xor_sync(0xFFFFFFFFu, v, off);

    if (lane == 0) out[warp_id] = v;
}

extern "C" void kernel_launch(void* const* d_in, const int* in_sizes, int n_in,
                              void* d_out, int out_size) {
    // Input order (metadata): features, agent_qs, adj, states, W, a
    const float* agent_qs = (const float*)d_in[1];
    float* out = (float*)d_out;

    const int nbatch = in_sizes[1] / N_AGENTS;  // 4096

    const int threads = 256;                    // 8 warps per block
    const int warps_per_block = threads / 32;
    const int blocks = (nbatch + warps_per_block - 1) / warps_per_block;

    noqmix_rowsum_kernel<<<blocks, threads>>>(agent_qs, out, nbatch);
}